// round 14
// baseline (speedup 1.0000x reference)
#include <cuda_runtime.h>
#include <cuda_bf16.h>
#include <cuda_fp16.h>
#include <cstring>

// KAN layer: y[b,o] = sum_f lerp(coeff[f, i-1, o], coeff[f, i, o], t) + bias[o]
// B=4096, F=128, G=64, OUT=64.  i = clip(ceil((x+3)*10.5), 1, 63); t = (x+3)*10.5-(i-1)
//
// R13: recombine proven-best pieces (census-driven):
//  - R11 interleaved row: lane's 8B = {c0 half2, d half2} -> ONE LDG.64/feature
//    (issue-bound kernel: 1 instr + 1 IADD beats 2xLDG.32 despite 2-line span)
//  - phase-1 in float domain: FRND(ceil), float clamps, single F2I + IMAD
//    (~8.5 instrs/feature, was ~9-12)
//  - 4-way HADD2 tree before one cvt + 2 FADD fp32 accumulate

#define F_DIM   128
#define G_SIZE  64
#define OUT_N   64
#define SPB     4
#define THREADS 256               // 8 warps = 4 samples x 2 feature-halves
#define B_TOTAL 4096
#define FH      64                // features per warp
#define ROW_BYTES 256

// interleaved fp16 tensor: [F][G][32 lanes][{c0.lo,c0.hi,d.lo,d.hi}] = 2 MB
__device__ __align__(16) __half g_ilv[F_DIM * G_SIZE * OUT_N * 2];

__global__ __launch_bounds__(256)
void kan_convert_kernel(const float* __restrict__ coeff)
{
    const int j  = blockIdx.x * 256 + threadIdx.x;   // 0..262143  (f,g,op)
    const int f  = j >> 11;
    const int g  = (j >> 5) & (G_SIZE - 1);
    const int op = j & 31;
    const int gn = min(g + 1, G_SIZE - 1);

    const float2 c0 = __ldg(reinterpret_cast<const float2*>(coeff + (f * G_SIZE + g ) * OUT_N) + op);
    const float2 c1 = __ldg(reinterpret_cast<const float2*>(coeff + (f * G_SIZE + gn) * OUT_N) + op);

    const __half2 h0 = __float22half2_rn(c0);
    const __half2 hd = __float22half2_rn(make_float2(c1.x - c0.x, c1.y - c0.y));

    uint2 v;
    memcpy(&v.x, &h0, 4);
    memcpy(&v.y, &hd, 4);
    reinterpret_cast<uint2*>(g_ilv)[j] = v;          // (f*G+g)*32 + op
}

__global__ __launch_bounds__(THREADS, 6)
void kan_main_kernel(const float* __restrict__ x,
                     const float* __restrict__ bias,
                     float* __restrict__ y)
{
    // sidx4[s*64+fp]: features {2fp,2fp+1} -> {off0, t0_h2, off1, t1_h2}
    __shared__ uint4  sidx4[SPB * F_DIM / 2];   // 4 KB
    __shared__ float2 part[SPB][32];            // 1 KB

    const int tid  = threadIdx.x;
    const int row0 = blockIdx.x * SPB;

    // ---- Phase 1: 2 consecutive features of one sample per thread ----
    {
        const int s  = tid >> 6;
        const int fp = tid & 63;
        const int f0 = fp << 1;
        const float2 xv = *reinterpret_cast<const float2*>(x + (row0 + s) * F_DIM + f0);

        uint4 e;
        {
            const float u = fmaf(xv.x, 10.5f, 31.5f);          // (x+3)*10.5
            float c = ceilf(u);                                // FRND
            c = fminf(fmaxf(c, 1.0f), 63.0f);                  // float clamps
            const float t = fmaf(xv.x, 10.5f, 32.5f) - c;      // u+1-c
            const __half2 th = __float2half2_rn(t);
            memcpy(&e.y, &th, 4);
            e.x = (unsigned)((int)c * ROW_BYTES                // IMAD + const
                             + (f0 * G_SIZE - 1) * ROW_BYTES);
        }
        {
            const float u = fmaf(xv.y, 10.5f, 31.5f);
            float c = ceilf(u);
            c = fminf(fmaxf(c, 1.0f), 63.0f);
            const float t = fmaf(xv.y, 10.5f, 32.5f) - c;
            const __half2 th = __float2half2_rn(t);
            memcpy(&e.w, &th, 4);
            e.z = (unsigned)((int)c * ROW_BYTES
                             + ((f0 + 1) * G_SIZE - 1) * ROW_BYTES);
        }
        sidx4[tid] = e;
    }
    __syncthreads();

    // ---- Phase 2: warp = (sample, feature-half); lane owns outputs {2l,2l+1} ----
    const int w    = tid >> 5;
    const int lane = tid & 31;
    const int s    = w >> 1;
    const int h    = w & 1;

    const uint4* sp = sidx4 + s * (F_DIM / 2) + h * (FH / 2);
    const char* base = reinterpret_cast<const char*>(g_ilv) + lane * 8;  // folded once

    float2 acc = make_float2(0.f, 0.f);

    #pragma unroll
    for (int q = 0; q < FH / 4; ++q) {             // 4 features per iteration
        const uint4 e0 = sp[2 * q];                // LDS.128 broadcast
        const uint4 e1 = sp[2 * q + 1];

        const uint2 v0 = *reinterpret_cast<const uint2*>(base + e0.x);  // one LDG.64/feature
        const uint2 v1 = *reinterpret_cast<const uint2*>(base + e0.z);
        const uint2 v2 = *reinterpret_cast<const uint2*>(base + e1.x);
        const uint2 v3 = *reinterpret_cast<const uint2*>(base + e1.z);

        __half2 c0a, d0a, c0b, d0b, c0c, d0c, c0d, d0d, t0, t1, t2, t3;
        memcpy(&c0a, &v0.x, 4); memcpy(&d0a, &v0.y, 4);
        memcpy(&c0b, &v1.x, 4); memcpy(&d0b, &v1.y, 4);
        memcpy(&c0c, &v2.x, 4); memcpy(&d0c, &v2.y, 4);
        memcpy(&c0d, &v3.x, 4); memcpy(&d0d, &v3.y, 4);
        memcpy(&t0, &e0.y, 4);  memcpy(&t1, &e0.w, 4);
        memcpy(&t2, &e1.y, 4);  memcpy(&t3, &e1.w, 4);

        const __half2 r0 = __hfma2(t0, d0a, c0a);
        const __half2 r1 = __hfma2(t1, d0b, c0b);
        const __half2 r2 = __hfma2(t2, d0c, c0c);
        const __half2 r3 = __hfma2(t3, d0d, c0d);

        const __half2 rs = __hadd2(__hadd2(r0, r1), __hadd2(r2, r3));
        const float2  rf = __half22float2(rs);
        acc.x += rf.x;
        acc.y += rf.y;
    }

    // ---- Phase 3: pair reduction + bias + store ----
    if (h == 1) part[s][lane] = acc;
    __syncthreads();
    if (h == 0) {
        const float2 pr = part[s][lane];
        const float2 bv = reinterpret_cast<const float2*>(bias)[lane];
        acc.x += pr.x + bv.x;
        acc.y += pr.y + bv.y;
        reinterpret_cast<float2*>(y + (row0 + s) * OUT_N)[lane] = acc;
    }
}

extern "C" void kernel_launch(void* const* d_in, const int* in_sizes, int n_in,
                              void* d_out, int out_size)
{
    const float* x     = (const float*)d_in[0];   // [4096, 128]
    const float* coeff = (const float*)d_in[1];   // [128, 64, 64]
    const float* bias  = (const float*)d_in[2];   // [64]
    float* y           = (float*)d_out;           // [4096, 64]

    kan_convert_kernel<<<F_DIM * G_SIZE * OUT_N / 2 / 256, 256>>>(coeff);
    kan_main_kernel<<<B_TOTAL / SPB, THREADS>>>(x, bias, y);
}

// round 15
// speedup vs baseline: 1.3178x; 1.3178x over previous
#include <cuda_runtime.h>
#include <cuda_bf16.h>
#include <cuda_fp16.h>
#include <cstring>

// KAN layer: y[b,o] = sum_f lerp(coeff[f, i-1, o], coeff[f, i, o], t) + bias[o]
// B=4096, F=128, G=64, OUT=64.  i = clip(ceil((x+3)*10.5), 1, 63); t = (x+3)*10.5-(i-1)
//
// R14: R13's full #pragma unroll front-batched the LDG stream -> cross-CTA
// L1tex queue contention (~1.7x at equal instr count). Recombine measured-best:
//  - phase-2 = R11 shape (one LDG.64/feature, e.x+lane8, BOUNDED unroll: 8
//    loads in flight)
//  - phase-1 = float-domain trim (FRND ceil + float clamps + one F2I + IMAD)
//  - 4-way HADD2 tree before one cvt + fp32 accumulate

#define F_DIM   128
#define G_SIZE  64
#define OUT_N   64
#define SPB     4
#define THREADS 256               // 8 warps = 4 samples x 2 feature-halves
#define B_TOTAL 4096
#define FH      64                // features per warp
#define ROW_BYTES 256

// interleaved fp16 tensor: [F][G][32 lanes][{c0.lo,c0.hi,d.lo,d.hi}] = 2 MB
__device__ __align__(16) __half g_ilv[F_DIM * G_SIZE * OUT_N * 2];

__global__ __launch_bounds__(256)
void kan_convert_kernel(const float* __restrict__ coeff)
{
    const int j  = blockIdx.x * 256 + threadIdx.x;   // 0..262143  (f,g,op)
    const int f  = j >> 11;
    const int g  = (j >> 5) & (G_SIZE - 1);
    const int op = j & 31;
    const int gn = min(g + 1, G_SIZE - 1);

    const float2 c0 = __ldg(reinterpret_cast<const float2*>(coeff + (f * G_SIZE + g ) * OUT_N) + op);
    const float2 c1 = __ldg(reinterpret_cast<const float2*>(coeff + (f * G_SIZE + gn) * OUT_N) + op);

    const __half2 h0 = __float22half2_rn(c0);
    const __half2 hd = __float22half2_rn(make_float2(c1.x - c0.x, c1.y - c0.y));

    uint2 v;
    memcpy(&v.x, &h0, 4);
    memcpy(&v.y, &hd, 4);
    reinterpret_cast<uint2*>(g_ilv)[j] = v;          // (f*G+g)*32 + op
}

__global__ __launch_bounds__(THREADS, 6)
void kan_main_kernel(const float* __restrict__ x,
                     const float* __restrict__ bias,
                     float* __restrict__ y)
{
    // sidx4[s*64+fp]: features {2fp,2fp+1} -> {off0, t0_h2, off1, t1_h2}
    __shared__ uint4  sidx4[SPB * F_DIM / 2];   // 4 KB
    __shared__ float2 part[SPB][32];            // 1 KB

    const int tid  = threadIdx.x;
    const int row0 = blockIdx.x * SPB;

    // ---- Phase 1: 2 consecutive features of one sample per thread ----
    {
        const int s  = tid >> 6;
        const int fp = tid & 63;
        const int f0 = fp << 1;
        const float2 xv = *reinterpret_cast<const float2*>(x + (row0 + s) * F_DIM + f0);

        uint4 e;
        {
            const float u = fmaf(xv.x, 10.5f, 31.5f);      // (x+3)*10.5
            float c = ceilf(u);
            c = fminf(fmaxf(c, 1.0f), 63.0f);
            const float t = fmaf(xv.x, 10.5f, 32.5f) - c;  // u+1-c
            const __half2 th = __float2half2_rn(t);
            memcpy(&e.y, &th, 4);
            e.x = (unsigned)((int)c * ROW_BYTES + (f0 * G_SIZE - 1) * ROW_BYTES);
        }
        {
            const float u = fmaf(xv.y, 10.5f, 31.5f);
            float c = ceilf(u);
            c = fminf(fmaxf(c, 1.0f), 63.0f);
            const float t = fmaf(xv.y, 10.5f, 32.5f) - c;
            const __half2 th = __float2half2_rn(t);
            memcpy(&e.w, &th, 4);
            e.z = (unsigned)((int)c * ROW_BYTES + ((f0 + 1) * G_SIZE - 1) * ROW_BYTES);
        }
        sidx4[tid] = e;
    }
    __syncthreads();

    // ---- Phase 2: warp = (sample, feature-half); lane owns outputs {2l,2l+1} ----
    const int w    = tid >> 5;
    const int lane = tid & 31;
    const int s    = w >> 1;
    const int h    = w & 1;

    const uint4* sp = sidx4 + s * (F_DIM / 2) + h * (FH / 2);
    const char* base = reinterpret_cast<const char*>(g_ilv);
    const unsigned lane8 = lane * 8;

    float2 acc = make_float2(0.f, 0.f);

    #pragma unroll 2
    for (int q = 0; q < FH / 4; ++q) {             // 4 features/iter, 8 in window
        const uint4 e0 = sp[2 * q];                // LDS.128 broadcast
        const uint4 e1 = sp[2 * q + 1];

        const uint2 v0 = *reinterpret_cast<const uint2*>(base + (e0.x + lane8));
        const uint2 v1 = *reinterpret_cast<const uint2*>(base + (e0.z + lane8));
        const uint2 v2 = *reinterpret_cast<const uint2*>(base + (e1.x + lane8));
        const uint2 v3 = *reinterpret_cast<const uint2*>(base + (e1.z + lane8));

        __half2 c0a, d0a, c0b, d0b, c0c, d0c, c0d, d0d, t0, t1, t2, t3;
        memcpy(&c0a, &v0.x, 4); memcpy(&d0a, &v0.y, 4);
        memcpy(&c0b, &v1.x, 4); memcpy(&d0b, &v1.y, 4);
        memcpy(&c0c, &v2.x, 4); memcpy(&d0c, &v2.y, 4);
        memcpy(&c0d, &v3.x, 4); memcpy(&d0d, &v3.y, 4);
        memcpy(&t0, &e0.y, 4);  memcpy(&t1, &e0.w, 4);
        memcpy(&t2, &e1.y, 4);  memcpy(&t3, &e1.w, 4);

        const __half2 r0 = __hfma2(t0, d0a, c0a);
        const __half2 r1 = __hfma2(t1, d0b, c0b);
        const __half2 r2 = __hfma2(t2, d0c, c0c);
        const __half2 r3 = __hfma2(t3, d0d, c0d);

        const __half2 rs = __hadd2(__hadd2(r0, r1), __hadd2(r2, r3));
        const float2  rf = __half22float2(rs);
        acc.x += rf.x;
        acc.y += rf.y;
    }

    // ---- Phase 3: pair reduction + bias + store ----
    if (h == 1) part[s][lane] = acc;
    __syncthreads();
    if (h == 0) {
        const float2 pr = part[s][lane];
        const float2 bv = reinterpret_cast<const float2*>(bias)[lane];
        acc.x += pr.x + bv.x;
        acc.y += pr.y + bv.y;
        reinterpret_cast<float2*>(y + (row0 + s) * OUT_N)[lane] = acc;
    }
}

extern "C" void kernel_launch(void* const* d_in, const int* in_sizes, int n_in,
                              void* d_out, int out_size)
{
    const float* x     = (const float*)d_in[0];   // [4096, 128]
    const float* coeff = (const float*)d_in[1];   // [128, 64, 64]
    const float* bias  = (const float*)d_in[2];   // [64]
    float* y           = (float*)d_out;           // [4096, 64]

    kan_convert_kernel<<<F_DIM * G_SIZE * OUT_N / 2 / 256, 256>>>(coeff);
    kan_main_kernel<<<B_TOTAL / SPB, THREADS>>>(x, bias, y);
}